// round 1
// baseline (speedup 1.0000x reference)
#include <cuda_runtime.h>
#include <stdint.h>

// TestSpatialTransform: reference collapses to two center crops
//   data_out = data[:, :, 16:176, 16:176, 16:176]   (trilinear at integer coords == gather)
//   seg_out  = seg [:, :, 16:176, 16:176, 16:176]
// Input tensors: (4,2,192,192,192) fp32 each. Output: concat(data_out, seg_out) flat.
//
// Pure HBM-bound copy. One float4 per thread; fully coalesced writes,
// 640B contiguous source rows at 64B-aligned offsets.

#define PATCH 160
#define SRC   192
#define OFF   16
#define BC    8                       // B*C = 4*2
#define W4    (PATCH / 4)             // 40 float4 per row
#define N_F4_PER_TENSOR (BC * PATCH * PATCH * W4)   // 8*160*160*40 = 8,192,000
#define N_F4_TOTAL      (2 * N_F4_PER_TENSOR)       // 16,384,000

__global__ void __launch_bounds__(256)
crop_copy_kernel(const float* __restrict__ data,
                 const float* __restrict__ seg,
                 float4* __restrict__ out)
{
    int idx = blockIdx.x * blockDim.x + threadIdx.x;
    if (idx >= N_F4_TOTAL) return;

    int w4 = idx % W4;
    int t  = idx / W4;
    int h  = t % PATCH; t /= PATCH;
    int d  = t % PATCH; t /= PATCH;
    int bc = t % BC;
    int tensor = t / BC;              // 0 = data, 1 = seg

    const float* src = tensor ? seg : data;

    // source flat index within (BC, 192,192,192)
    int sidx = (((bc * SRC) + (d + OFF)) * SRC + (h + OFF)) * SRC + OFF + (w4 << 2);

    out[idx] = *reinterpret_cast<const float4*>(src + sidx);
}

extern "C" void kernel_launch(void* const* d_in, const int* in_sizes, int n_in,
                              void* d_out, int out_size)
{
    const float* data = (const float*)d_in[0];
    const float* seg  = (const float*)d_in[1];
    float4* out = (float4*)d_out;

    const int threads = 256;
    const int blocks  = (N_F4_TOTAL + threads - 1) / threads;  // 64000
    crop_copy_kernel<<<blocks, threads>>>(data, seg, out);
}

// round 2
// speedup vs baseline: 1.0195x; 1.0195x over previous
#include <cuda_runtime.h>
#include <stdint.h>

// TestSpatialTransform == two center crops:
//   out[0:N)   = data[:, :, 16:176, 16:176, 16:176]
//   out[N:2N)  = seg [:, :, 16:176, 16:176, 16:176]
// Pure HBM copy. Each thread handles ONE crop position in BOTH tensors:
// one index computation -> 2 independent LDG.128 + 2 STG.128 (MLP=2/warp-slot),
// half the grid, half the integer overhead per byte moved.

#define PATCH 160
#define SRC   192
#define OFF   16
#define BC    8                       // B*C = 4*2
#define W4    (PATCH / 4)             // 40 float4 per row
#define N_F4_PER_TENSOR (BC * PATCH * PATCH * W4)   // 8,192,000

__global__ void __launch_bounds__(256)
crop_copy2_kernel(const float* __restrict__ data,
                  const float* __restrict__ seg,
                  float4* __restrict__ out)
{
    int idx = blockIdx.x * blockDim.x + threadIdx.x;
    if (idx >= N_F4_PER_TENSOR) return;

    int w4 = idx % W4;
    int t  = idx / W4;
    int h  = t % PATCH; t /= PATCH;
    int d  = t % PATCH;
    int bc = t / PATCH;

    // source flat float index within (BC, 192, 192, 192)
    int sidx = (((bc * SRC) + (d + OFF)) * SRC + (h + OFF)) * SRC + OFF + (w4 << 2);

    // two independent streaming loads (deep L1tex queue), then two stores
    float4 a = __ldcs(reinterpret_cast<const float4*>(data + sidx));
    float4 b = __ldcs(reinterpret_cast<const float4*>(seg  + sidx));

    __stcs(out + idx, a);
    __stcs(out + idx + N_F4_PER_TENSOR, b);
}

extern "C" void kernel_launch(void* const* d_in, const int* in_sizes, int n_in,
                              void* d_out, int out_size)
{
    const float* data = (const float*)d_in[0];
    const float* seg  = (const float*)d_in[1];
    float4* out = (float4*)d_out;

    const int threads = 256;
    const int blocks  = (N_F4_PER_TENSOR + threads - 1) / threads;  // 32000
    crop_copy2_kernel<<<blocks, threads>>>(data, seg, out);
}